// round 3
// baseline (speedup 1.0000x reference)
#include <cuda_runtime.h>

#define NRELS 19
#define CPAD  20          // padded cnt row (16B-aligned int4 loads)
#define DIM   32
#define MAXN  100000
#define MAXE  1600000

// ---------------- static scratch (no allocation allowed) ----------------
static __device__ int4   g_cnt4[MAXN * (CPAD / 4)];   // per (node, rel) counts, padded rows
static __device__ float  g_h1[MAXN * DIM];            // layer-1 activations
static __device__ float4 g_h2[MAXN * (DIM / 4)];      // layer-2 accumulator
static __device__ int2   g_edata[MAXE];               // relation-bucketed (src, dst)
static __device__ int    g_relHist[NRELS];
static __device__ int    g_relOff[NRELS + 1];
static __device__ int    g_relCur[NRELS];

// ---------------- sm_103a packed-fp32 + vector-red helpers ----------------
__device__ __forceinline__ unsigned long long pack2(float lo, float hi) {
    unsigned long long r;
    asm("mov.b64 %0, {%1, %2};" : "=l"(r) : "f"(lo), "f"(hi));
    return r;
}
__device__ __forceinline__ float2 unpack2(unsigned long long v) {
    float2 r;
    asm("mov.b64 {%0, %1}, %2;" : "=f"(r.x), "=f"(r.y) : "l"(v));
    return r;
}
__device__ __forceinline__ void fma2(unsigned long long& acc, unsigned long long a,
                                     unsigned long long b) {
    asm("fma.rn.f32x2 %0, %1, %2, %0;" : "+l"(acc) : "l"(a), "l"(b));
}
__device__ __forceinline__ void red4(float* p, float a, float b, float c, float d) {
    asm volatile("red.global.add.v4.f32 [%0], {%1, %2, %3, %4};"
                 :: "l"(p), "f"(a), "f"(b), "f"(c), "f"(d) : "memory");
}

// ---------------- kernels ----------------

__global__ void k_zero(int N) {
    int stride = gridDim.x * blockDim.x;
    int tid = blockIdx.x * blockDim.x + threadIdx.x;
    int4* c4 = g_cnt4;
    int tot4 = N * (CPAD / 4);
    for (int i = tid; i < tot4; i += stride) c4[i] = make_int4(0, 0, 0, 0);
    if (tid < NRELS) g_relHist[tid] = 0;
}

// Per-(dst,rel) counts + relation histogram, 4 edges per thread (int4 loads).
__global__ void k_hist(const int* __restrict__ dst, const int* __restrict__ et, int E) {
    __shared__ int sh[NRELS];
    if (threadIdx.x < NRELS) sh[threadIdx.x] = 0;
    __syncthreads();
    int* cnt = (int*)g_cnt4;
    int e0 = (blockIdx.x * blockDim.x + threadIdx.x) * 4;
    if (e0 + 3 < E) {
        int4 d4 = *(const int4*)&dst[e0];
        int4 r4 = *(const int4*)&et[e0];
        atomicAdd(&cnt[d4.x * CPAD + r4.x], 1);
        atomicAdd(&cnt[d4.y * CPAD + r4.y], 1);
        atomicAdd(&cnt[d4.z * CPAD + r4.z], 1);
        atomicAdd(&cnt[d4.w * CPAD + r4.w], 1);
        atomicAdd(&sh[r4.x], 1); atomicAdd(&sh[r4.y], 1);
        atomicAdd(&sh[r4.z], 1); atomicAdd(&sh[r4.w], 1);
    } else {
        for (int e = e0; e < E; e++) {
            int r = et[e];
            atomicAdd(&cnt[dst[e] * CPAD + r], 1);
            atomicAdd(&sh[r], 1);
        }
    }
    __syncthreads();
    if (threadIdx.x < NRELS) atomicAdd(&g_relHist[threadIdx.x], sh[threadIdx.x]);
}

__global__ void k_scan() {
    if (threadIdx.x == 0) {
        int s = 0;
        for (int r = 0; r < NRELS; r++) {
            g_relOff[r] = s;
            g_relCur[r] = s;
            s += g_relHist[r];
        }
        g_relOff[NRELS] = s;
    }
}

// Counting-sort scatter by relation, 4 edges/thread, block-aggregated cursors.
__global__ void k_scatter(const int* __restrict__ src, const int* __restrict__ dst,
                          const int* __restrict__ et, int E) {
    __shared__ int shCnt[NRELS];
    __shared__ int shBase[NRELS];
    int t = threadIdx.x;
    if (t < NRELS) shCnt[t] = 0;
    __syncthreads();
    int e0 = (blockIdx.x * blockDim.x + t) * 4;
    int r[4], s[4], d[4], lp[4];
    int cnt = 0;
    if (e0 + 3 < E) {
        int4 s4 = *(const int4*)&src[e0];
        int4 d4 = *(const int4*)&dst[e0];
        int4 r4 = *(const int4*)&et[e0];
        s[0]=s4.x; s[1]=s4.y; s[2]=s4.z; s[3]=s4.w;
        d[0]=d4.x; d[1]=d4.y; d[2]=d4.z; d[3]=d4.w;
        r[0]=r4.x; r[1]=r4.y; r[2]=r4.z; r[3]=r4.w;
        cnt = 4;
    } else {
        for (int e = e0; e < E; e++) {
            s[cnt]=src[e]; d[cnt]=dst[e]; r[cnt]=et[e]; cnt++;
        }
    }
    for (int k = 0; k < cnt; k++) lp[k] = atomicAdd(&shCnt[r[k]], 1);
    __syncthreads();
    if (t < NRELS) shBase[t] = atomicAdd(&g_relCur[t], shCnt[t]);
    __syncthreads();
    for (int k = 0; k < cnt; k++)
        g_edata[shBase[r[k]] + lp[k]] = make_int2(s[k], d[k]);
}

// Layer 1: h1[v,o] = relu(b1[o] + sum_r cnt[v,r] * W1[r,o]).  Warp per node,
// cnt row read as 5 broadcast LDG.128.  Also zeroes the h2 accumulator.
__global__ void k_layer1(const float* __restrict__ W1, const float* __restrict__ b1, int N) {
    __shared__ float sW[NRELS * DIM];
    __shared__ float sb[DIM];
    int t = threadIdx.x;
    // zero h2 (needed before k_layer2's reductions)
    {
        float* h2 = (float*)g_h2;
        int tot = N * DIM;
        for (int i = blockIdx.x * blockDim.x + t; i < tot; i += gridDim.x * blockDim.x)
            h2[i] = 0.0f;
    }
    for (int i = t; i < NRELS * DIM; i += blockDim.x) sW[i] = W1[i];
    if (t < DIM) sb[t] = b1[t];
    __syncthreads();
    int lane = t & 31;
    int wpb = blockDim.x >> 5;
    for (int v = blockIdx.x * wpb + (t >> 5); v < N; v += gridDim.x * wpb) {
        const int4* crow = &g_cnt4[v * (CPAD / 4)];
        int c[CPAD];
#pragma unroll
        for (int q = 0; q < CPAD / 4; q++) {
            int4 cc = __ldg(&crow[q]);
            c[q * 4 + 0] = cc.x; c[q * 4 + 1] = cc.y;
            c[q * 4 + 2] = cc.z; c[q * 4 + 3] = cc.w;
        }
        float acc = sb[lane];
#pragma unroll
        for (int r = 0; r < NRELS; r++)
            acc += (float)c[r] * sW[r * DIM + lane];
        g_h1[v * DIM + lane] = fmaxf(acc, 0.0f);
    }
}

// Layer 2 (hot): per warp, 8 edges per chunk.
//  - W2[rel] register-resident (16 f32x2 per lane, lane = output column)
//  - edata for 8 edges in ONE coalesced LDG.64 (lanes 0-7), src/dst via shfl
//  - double-buffered h registers: next chunk's 8 gathers in flight during compute
//  - staged h read back as ulonglong2 (operand pairs pre-packed, no movs)
//  - 2 red.global.add.v4 waves per chunk; padded edges add exact 0.0 to node 0
__global__ void __launch_bounds__(128, 5) k_layer2(const float* __restrict__ W2,
                                                   int E, int nWarps) {
    __shared__ float shh[4][8][DIM];    // [warp][edge][i]
    __shared__ float sacc[4][8][DIM];   // [warp][edge][col]
    __shared__ int sOff[NRELS + 1];
    int t = threadIdx.x;
    if (t <= NRELS) sOff[t] = g_relOff[t];
    __syncthreads();
    int lane = t & 31;
    int warp = t >> 5;
    int grp  = lane >> 3;          // edge-in-wave for the reduction
    int cg4  = (lane & 7) * 4;     // column group for the reduction

    int gw = blockIdx.x * 4 + warp;
    if (gw >= nWarps) return;
    int e    = (int)(((long long)gw * E) / nWarps);
    int eEnd = (int)(((long long)(gw + 1) * E) / nWarps);

    int r = 0;
    while (e < eEnd) {
        while (sOff[r + 1] <= e) r++;               // edges are relation-sorted
        int runEnd = min(eEnd, sOff[r + 1]);
        if (e >= runEnd) continue;
        const float* Wr = W2 + r * DIM * DIM;
        unsigned long long w[16];
#pragma unroll
        for (int i = 0; i < 16; i++)
            w[i] = pack2(__ldg(&Wr[(2 * i) * DIM + lane]),
                         __ldg(&Wr[(2 * i + 1) * DIM + lane]));

        // prologue: edata + h for first chunk
        int2 edc = make_int2(0, 0);
        if (lane < 8 && e + lane < runEnd) edc = __ldg(&g_edata[e + lane]);
        float hA[8];
#pragma unroll
        for (int k = 0; k < 8; k++) {
            int sk = __shfl_sync(0xffffffffu, edc.x, k);
            hA[k] = (e + k < runEnd) ? __ldg(&g_h1[sk * DIM + lane]) : 0.0f;
        }

        for (int c = e; c < runEnd; c += 8) {
            // fetch next chunk's edata (one coalesced LDG.64)
            int cn = c + 8;
            int2 edn = make_int2(0, 0);
            if (lane < 8 && cn + lane < runEnd) edn = __ldg(&g_edata[cn + lane]);

            // stage current chunk's h
#pragma unroll
            for (int k = 0; k < 8; k++) shh[warp][k][lane] = hA[k];
            __syncwarp();

            // prefetch next chunk's h (8 LDGs in flight during compute)
#pragma unroll
            for (int k = 0; k < 8; k++) {
                int sk = __shfl_sync(0xffffffffu, edn.x, k);
                hA[k] = (cn + k < runEnd) ? __ldg(&g_h1[sk * DIM + lane]) : 0.0f;
            }

            // 8 interleaved GEMV chains, operands pre-packed in SMEM
            unsigned long long ac[8];
#pragma unroll
            for (int k = 0; k < 8; k++) ac[k] = 0ull;
#pragma unroll
            for (int jp = 0; jp < 8; jp++) {
#pragma unroll
                for (int k = 0; k < 8; k++) {
                    ulonglong2 p = *(const ulonglong2*)&shh[warp][k][jp * 4];
                    fma2(ac[k], p.x, w[2 * jp]);
                    fma2(ac[k], p.y, w[2 * jp + 1]);
                }
            }
#pragma unroll
            for (int k = 0; k < 8; k++) {
                float2 a = unpack2(ac[k]);
                sacc[warp][k][lane] = a.x + a.y;
            }
            __syncwarp();

            // two vector-reduction waves: 4 edges per wave, 8 lanes x 4 cols each
#pragma unroll
            for (int wv = 0; wv < 2; wv++) {
                int eidx = wv * 4 + grp;
                int dsel = __shfl_sync(0xffffffffu, edc.y, eidx);
                float4 v = *(const float4*)&sacc[warp][eidx][cg4];
                red4(((float*)g_h2) + (size_t)dsel * DIM + cg4, v.x, v.y, v.z, v.w);
            }
            edc = edn;
        }
        e = runEnd;
    }
}

// Final: out[v] = relu(h2acc[v] + b2) @ W3 + b3.  Warp per node, shfl-broadcast h.
__global__ void k_final(const float* __restrict__ W3, const float* __restrict__ b2,
                        const float* __restrict__ b3, float* __restrict__ out, int N) {
    __shared__ float sW[DIM * DIM];
    __shared__ float sb2[DIM];
    __shared__ float sb3[DIM];
    int t = threadIdx.x;
    for (int i = t; i < DIM * DIM; i += blockDim.x) sW[i] = W3[i];
    if (t < DIM) { sb2[t] = b2[t]; sb3[t] = b3[t]; }
    __syncthreads();
    int lane = t & 31;
    int wpb = blockDim.x >> 5;
    for (int v = blockIdx.x * wpb + (t >> 5); v < N; v += gridDim.x * wpb) {
        float h = fmaxf(((const float*)g_h2)[v * DIM + lane] + sb2[lane], 0.0f);
        float acc = sb3[lane];
#pragma unroll
        for (int i = 0; i < DIM; i++) {
            float hi = __shfl_sync(0xffffffffu, h, i);
            acc += hi * sW[i * DIM + lane];
        }
        out[v * DIM + lane] = acc;
    }
}

// ---------------- launch ----------------
extern "C" void kernel_launch(void* const* d_in, const int* in_sizes, int n_in,
                              void* d_out, int out_size) {
    const int* src = (const int*)d_in[0];
    const int* dst = (const int*)d_in[1];
    const int* et  = (const int*)d_in[2];
    int base = (n_in > 3 && in_sizes[3] == 1) ? 4 : 3;
    const float* W1 = (const float*)d_in[base + 0];
    const float* b1 = (const float*)d_in[base + 1];
    const float* W2 = (const float*)d_in[base + 2];
    const float* b2 = (const float*)d_in[base + 3];
    const float* W3 = (const float*)d_in[base + 4];
    const float* b3 = (const float*)d_in[base + 5];

    int E = in_sizes[0];
    int N = out_size / DIM;
    float* out = (float*)d_out;

    k_zero<<<1024, 256>>>(N);
    int edgeBlocks4 = (E / 4 + 255) / 256 + 1;
    k_hist<<<edgeBlocks4, 256>>>(dst, et, E);
    k_scan<<<1, 32>>>();
    k_scatter<<<edgeBlocks4, 256>>>(src, dst, et, E);

    int nodeBlocks = (N + 7) / 8;
    k_layer1<<<nodeBlocks, 256>>>(W1, b1, N);

    const int nWarps = 2960;   // 148 SMs x 5 blocks x 4 warps -> one balanced wave
    k_layer2<<<nWarps / 4, 128>>>(W2, E, nWarps);

    k_final<<<nodeBlocks, 256>>>(W3, b2, b3, out, N);
}

// round 6
// speedup vs baseline: 1.5709x; 1.5709x over previous
#include <cuda_runtime.h>

#define NRELS 19
#define CPAD  20          // padded cnt row (16B-aligned int4 loads)
#define DIM   32
#define MAXN  100000
#define MAXE  1600000

// ---------------- static scratch (no allocation allowed) ----------------
static __device__ int4   g_cnt4[MAXN * (CPAD / 4)];   // per (node, rel) counts, padded rows
static __device__ float  g_h1[MAXN * DIM];            // layer-1 activations
static __device__ float4 g_h2[MAXN * (DIM / 4)];      // layer-2 accumulator
static __device__ int2   g_edata[MAXE];               // relation-bucketed (src, dst)
static __device__ int    g_relHist[NRELS];
static __device__ int    g_relOff[NRELS + 1];
static __device__ int    g_relCur[NRELS];

// ---------------- sm_103a packed-fp32 + vector-red helpers ----------------
__device__ __forceinline__ unsigned long long pack2(float lo, float hi) {
    unsigned long long r;
    asm("mov.b64 %0, {%1, %2};" : "=l"(r) : "f"(lo), "f"(hi));
    return r;
}
__device__ __forceinline__ float2 unpack2(unsigned long long v) {
    float2 r;
    asm("mov.b64 {%0, %1}, %2;" : "=f"(r.x), "=f"(r.y) : "l"(v));
    return r;
}
__device__ __forceinline__ void fma2(unsigned long long& acc, unsigned long long a,
                                     unsigned long long b) {
    asm("fma.rn.f32x2 %0, %1, %2, %0;" : "+l"(acc) : "l"(a), "l"(b));
}
__device__ __forceinline__ void red4(float* p, float a, float b, float c, float d) {
    asm volatile("red.global.add.v4.f32 [%0], {%1, %2, %3, %4};"
                 :: "l"(p), "f"(a), "f"(b), "f"(c), "f"(d) : "memory");
}

// ---------------- kernels ----------------

__global__ void k_zero(int N) {
    int stride = gridDim.x * blockDim.x;
    int tid = blockIdx.x * blockDim.x + threadIdx.x;
    int4* c4 = g_cnt4;
    int tot4 = N * (CPAD / 4);
    for (int i = tid; i < tot4; i += stride) c4[i] = make_int4(0, 0, 0, 0);
    if (tid < NRELS) g_relHist[tid] = 0;
}

// Per-(dst,rel) counts + relation histogram, 4 edges per thread (int4 loads).
__global__ void k_hist(const int* __restrict__ dst, const int* __restrict__ et, int E) {
    __shared__ int sh[NRELS];
    if (threadIdx.x < NRELS) sh[threadIdx.x] = 0;
    __syncthreads();
    int* cnt = (int*)g_cnt4;
    int e0 = (blockIdx.x * blockDim.x + threadIdx.x) * 4;
    if (e0 + 3 < E) {
        int4 d4 = *(const int4*)&dst[e0];
        int4 r4 = *(const int4*)&et[e0];
        atomicAdd(&cnt[d4.x * CPAD + r4.x], 1);
        atomicAdd(&cnt[d4.y * CPAD + r4.y], 1);
        atomicAdd(&cnt[d4.z * CPAD + r4.z], 1);
        atomicAdd(&cnt[d4.w * CPAD + r4.w], 1);
        atomicAdd(&sh[r4.x], 1); atomicAdd(&sh[r4.y], 1);
        atomicAdd(&sh[r4.z], 1); atomicAdd(&sh[r4.w], 1);
    } else {
        for (int e = e0; e < E; e++) {
            int r = et[e];
            atomicAdd(&cnt[dst[e] * CPAD + r], 1);
            atomicAdd(&sh[r], 1);
        }
    }
    __syncthreads();
    if (threadIdx.x < NRELS) atomicAdd(&g_relHist[threadIdx.x], sh[threadIdx.x]);
}

__global__ void k_scan() {
    if (threadIdx.x == 0) {
        int s = 0;
        for (int r = 0; r < NRELS; r++) {
            g_relOff[r] = s;
            g_relCur[r] = s;
            s += g_relHist[r];
        }
        g_relOff[NRELS] = s;
    }
}

// Counting-sort scatter by relation, 4 edges/thread, block-aggregated cursors.
__global__ void k_scatter(const int* __restrict__ src, const int* __restrict__ dst,
                          const int* __restrict__ et, int E) {
    __shared__ int shCnt[NRELS];
    __shared__ int shBase[NRELS];
    int t = threadIdx.x;
    if (t < NRELS) shCnt[t] = 0;
    __syncthreads();
    int e0 = (blockIdx.x * blockDim.x + t) * 4;
    int r[4], s[4], d[4], lp[4];
    int cnt = 0;
    if (e0 + 3 < E) {
        int4 s4 = *(const int4*)&src[e0];
        int4 d4 = *(const int4*)&dst[e0];
        int4 r4 = *(const int4*)&et[e0];
        s[0]=s4.x; s[1]=s4.y; s[2]=s4.z; s[3]=s4.w;
        d[0]=d4.x; d[1]=d4.y; d[2]=d4.z; d[3]=d4.w;
        r[0]=r4.x; r[1]=r4.y; r[2]=r4.z; r[3]=r4.w;
        cnt = 4;
    } else {
        for (int e = e0; e < E; e++) {
            s[cnt]=src[e]; d[cnt]=dst[e]; r[cnt]=et[e]; cnt++;
        }
    }
    for (int k = 0; k < cnt; k++) lp[k] = atomicAdd(&shCnt[r[k]], 1);
    __syncthreads();
    if (t < NRELS) shBase[t] = atomicAdd(&g_relCur[t], shCnt[t]);
    __syncthreads();
    for (int k = 0; k < cnt; k++)
        g_edata[shBase[r[k]] + lp[k]] = make_int2(s[k], d[k]);
}

// Layer 1: h1[v,o] = relu(b1[o] + sum_r cnt[v,r] * W1[r,o]).  Warp per node,
// cnt row read as 5 broadcast LDG.128.  Also zeroes the h2 accumulator.
__global__ void k_layer1(const float* __restrict__ W1, const float* __restrict__ b1, int N) {
    __shared__ float sW[NRELS * DIM];
    __shared__ float sb[DIM];
    int t = threadIdx.x;
    {
        float* h2 = (float*)g_h2;
        int tot = N * DIM;
        for (int i = blockIdx.x * blockDim.x + t; i < tot; i += gridDim.x * blockDim.x)
            h2[i] = 0.0f;
    }
    for (int i = t; i < NRELS * DIM; i += blockDim.x) sW[i] = W1[i];
    if (t < DIM) sb[t] = b1[t];
    __syncthreads();
    int lane = t & 31;
    int wpb = blockDim.x >> 5;
    for (int v = blockIdx.x * wpb + (t >> 5); v < N; v += gridDim.x * wpb) {
        const int4* crow = &g_cnt4[v * (CPAD / 4)];
        int c[CPAD];
#pragma unroll
        for (int q = 0; q < CPAD / 4; q++) {
            int4 cc = __ldg(&crow[q]);
            c[q * 4 + 0] = cc.x; c[q * 4 + 1] = cc.y;
            c[q * 4 + 2] = cc.z; c[q * 4 + 3] = cc.w;
        }
        float acc = sb[lane];
#pragma unroll
        for (int r = 0; r < NRELS; r++)
            acc += (float)c[r] * sW[r * DIM + lane];
        g_h1[v * DIM + lane] = fmaxf(acc, 0.0f);
    }
}

// Layer 2 (hot): per warp, 8 edges staged per chunk, computed in TWO passes of
// 4 accumulator chains (keeps live registers ~73, no spills):
//  - W2[rel] register-resident (16 f32x2 per lane, lane = output column)
//  - edata for 8 edges in ONE coalesced LDG.64 (lanes 0-7), src/dst via shfl
//  - double-buffered h registers: next chunk's 8 gathers in flight during compute
//  - staged h read back as ulonglong2 (operand pairs pre-packed, no movs)
//  - one red.global.add.v4 wave per 4-edge half; padded edges add exact 0.0
__global__ void __launch_bounds__(128, 4) k_layer2(const float* __restrict__ W2,
                                                   int E, int nWarps) {
    __shared__ float shh[4][8][DIM];    // [warp][edge][i]
    __shared__ float sacc[4][4][DIM];   // [warp][edge-in-half][col]
    __shared__ int sOff[NRELS + 1];
    int t = threadIdx.x;
    if (t <= NRELS) sOff[t] = g_relOff[t];
    __syncthreads();
    int lane = t & 31;
    int warp = t >> 5;
    int grp  = lane >> 3;          // edge-in-half for the reduction
    int cg4  = (lane & 7) * 4;     // column group for the reduction

    int gw = blockIdx.x * 4 + warp;
    if (gw >= nWarps) return;
    int e    = (int)(((long long)gw * E) / nWarps);
    int eEnd = (int)(((long long)(gw + 1) * E) / nWarps);

    int r = 0;
    while (e < eEnd) {
        while (sOff[r + 1] <= e) r++;               // edges are relation-sorted
        int runEnd = min(eEnd, sOff[r + 1]);
        if (e >= runEnd) continue;
        const float* Wr = W2 + r * DIM * DIM;
        unsigned long long w[16];
#pragma unroll
        for (int i = 0; i < 16; i++)
            w[i] = pack2(__ldg(&Wr[(2 * i) * DIM + lane]),
                         __ldg(&Wr[(2 * i + 1) * DIM + lane]));

        // prologue: edata + h for first chunk
        int2 edc = make_int2(0, 0);
        if (lane < 8 && e + lane < runEnd) edc = __ldg(&g_edata[e + lane]);
        float hA[8];
#pragma unroll
        for (int k = 0; k < 8; k++) {
            int sk = __shfl_sync(0xffffffffu, edc.x, k);
            hA[k] = (e + k < runEnd) ? __ldg(&g_h1[sk * DIM + lane]) : 0.0f;
        }

        for (int c = e; c < runEnd; c += 8) {
            // stage current chunk's h
#pragma unroll
            for (int k = 0; k < 8; k++) shh[warp][k][lane] = hA[k];
            __syncwarp();

            // fetch next chunk's edata (one coalesced LDG.64)
            int cn = c + 8;
            int2 edn = make_int2(0, 0);
            if (lane < 8 && cn + lane < runEnd) edn = __ldg(&g_edata[cn + lane]);
            // prefetch next chunk's h (8 LDGs in flight during compute)
#pragma unroll
            for (int k = 0; k < 8; k++) {
                int sk = __shfl_sync(0xffffffffu, edn.x, k);
                hA[k] = (cn + k < runEnd) ? __ldg(&g_h1[sk * DIM + lane]) : 0.0f;
            }

            // two compute passes of 4 interleaved GEMV chains each
#pragma unroll
            for (int half = 0; half < 2; half++) {
                unsigned long long ac0 = 0ull, ac1 = 0ull, ac2 = 0ull, ac3 = 0ull;
#pragma unroll
                for (int jp = 0; jp < 8; jp++) {
                    ulonglong2 p0 = *(const ulonglong2*)&shh[warp][half * 4 + 0][jp * 4];
                    ulonglong2 p1 = *(const ulonglong2*)&shh[warp][half * 4 + 1][jp * 4];
                    ulonglong2 p2 = *(const ulonglong2*)&shh[warp][half * 4 + 2][jp * 4];
                    ulonglong2 p3 = *(const ulonglong2*)&shh[warp][half * 4 + 3][jp * 4];
                    fma2(ac0, p0.x, w[2 * jp]);
                    fma2(ac1, p1.x, w[2 * jp]);
                    fma2(ac2, p2.x, w[2 * jp]);
                    fma2(ac3, p3.x, w[2 * jp]);
                    fma2(ac0, p0.y, w[2 * jp + 1]);
                    fma2(ac1, p1.y, w[2 * jp + 1]);
                    fma2(ac2, p2.y, w[2 * jp + 1]);
                    fma2(ac3, p3.y, w[2 * jp + 1]);
                }
                float2 a;
                a = unpack2(ac0); sacc[warp][0][lane] = a.x + a.y;
                a = unpack2(ac1); sacc[warp][1][lane] = a.x + a.y;
                a = unpack2(ac2); sacc[warp][2][lane] = a.x + a.y;
                a = unpack2(ac3); sacc[warp][3][lane] = a.x + a.y;
                __syncwarp();

                // one vector-reduction wave: 4 edges, 8 lanes x 4 cols each
                int dsel = __shfl_sync(0xffffffffu, edc.y, half * 4 + grp);
                float4 v = *(const float4*)&sacc[warp][grp][cg4];
                red4(((float*)g_h2) + (size_t)dsel * DIM + cg4, v.x, v.y, v.z, v.w);
                __syncwarp();   // sacc reused by next half
            }
            edc = edn;
        }
        e = runEnd;
    }
}

// Final: out[v] = relu(h2acc[v] + b2) @ W3 + b3.  Warp per node, shfl-broadcast h.
__global__ void k_final(const float* __restrict__ W3, const float* __restrict__ b2,
                        const float* __restrict__ b3, float* __restrict__ out, int N) {
    __shared__ float sW[DIM * DIM];
    __shared__ float sb2[DIM];
    __shared__ float sb3[DIM];
    int t = threadIdx.x;
    for (int i = t; i < DIM * DIM; i += blockDim.x) sW[i] = W3[i];
    if (t < DIM) { sb2[t] = b2[t]; sb3[t] = b3[t]; }
    __syncthreads();
    int lane = t & 31;
    int wpb = blockDim.x >> 5;
    for (int v = blockIdx.x * wpb + (t >> 5); v < N; v += gridDim.x * wpb) {
        float h = fmaxf(((const float*)g_h2)[v * DIM + lane] + sb2[lane], 0.0f);
        float acc = sb3[lane];
#pragma unroll
        for (int i = 0; i < DIM; i++) {
            float hi = __shfl_sync(0xffffffffu, h, i);
            acc += hi * sW[i * DIM + lane];
        }
        out[v * DIM + lane] = acc;
    }
}

// ---------------- launch ----------------
extern "C" void kernel_launch(void* const* d_in, const int* in_sizes, int n_in,
                              void* d_out, int out_size) {
    const int* src = (const int*)d_in[0];
    const int* dst = (const int*)d_in[1];
    const int* et  = (const int*)d_in[2];
    int base = (n_in > 3 && in_sizes[3] == 1) ? 4 : 3;
    const float* W1 = (const float*)d_in[base + 0];
    const float* b1 = (const float*)d_in[base + 1];
    const float* W2 = (const float*)d_in[base + 2];
    const float* b2 = (const float*)d_in[base + 3];
    const float* W3 = (const float*)d_in[base + 4];
    const float* b3 = (const float*)d_in[base + 5];

    int E = in_sizes[0];
    int N = out_size / DIM;
    float* out = (float*)d_out;

    k_zero<<<1024, 256>>>(N);
    int edgeBlocks4 = (E / 4 + 255) / 256 + 1;
    k_hist<<<edgeBlocks4, 256>>>(dst, et, E);
    k_scan<<<1, 32>>>();
    k_scatter<<<edgeBlocks4, 256>>>(src, dst, et, E);

    int nodeBlocks = (N + 7) / 8;
    k_layer1<<<nodeBlocks, 256>>>(W1, b1, N);

    const int nWarps = 2368;   // 148 SMs x 4 blocks x 4 warps -> one balanced wave
    k_layer2<<<nWarps / 4, 128>>>(W2, E, nWarps);

    k_final<<<nodeBlocks, 256>>>(W3, b2, b3, out, N);
}